// round 9
// baseline (speedup 1.0000x reference)
#include <cuda_runtime.h>
#include <cstdint>

// ============================================================================
// CausalAttention, B=4, S=4096, D=1024, fp32 in/out.
// bf16x3-split mma.sync m16n8k16 GEMMs with WARP SPECIALIZATION:
//   warps 0-7  : consumers — ldmatrix.x4 fragment loads + MMAs only
//   warps 8-11 : producers — LDG fp32, split into hi/lo bf16x2, STS into
//                double-buffered pair-line-swizzled smem tiles
// Handshake: named barriers full[st]/free[st] (arrive/sync, count=384),
// membar.cta release before producer arrive. No __syncthreads in the loop.
// ============================================================================

static constexpr int Bb = 4;
static constexpr int S  = 4096;
static constexpr int D  = 1024;
static constexpr int BM = 128;
static constexpr int BN = 128;
static constexpr int BK = 32;                 // floats per chunk (16 words)
static constexpr int NTHREADS = 384;

static constexpr int TILE_W    = 2048;        // words per [128][16] tile (8 KB)
static constexpr int STAGE_W   = 4 * TILE_W;  // Ah, Al, Bh, Bl
static constexpr int SMEM_BYTES = 2 * STAGE_W * 4;   // 65536

static __device__ float g_q [(size_t)Bb * S * D];
static __device__ float g_k [(size_t)Bb * S * D];
static __device__ float g_v [(size_t)Bb * S * D];
static __device__ float g_vt[(size_t)Bb * D * S];
static __device__ float g_wt[(size_t)3 * D * D];
static __device__ float g_s [(size_t)Bb * S * S];

// ---------------------------------------------------------------------------
// swizzled word index of (row, w) inside a [128][16]-word tile
__device__ __forceinline__ uint32_t tile_addr(uint32_t row, uint32_t w) {
    const uint32_t line = row >> 1;
    const uint32_t off  = ((row & 1u) << 4) + w;
    return line * 32u + (off ^ ((line & 7u) << 2));
}

__device__ __forceinline__ uint32_t smem_u32(const void* p) {
    uint32_t a;
    asm("{ .reg .u64 t; cvta.to.shared.u64 t, %1; cvt.u32.u64 %0, t; }"
        : "=r"(a) : "l"(p));
    return a;
}

__device__ __forceinline__ void ldsm_x4(uint32_t (&r)[4], uint32_t saddr) {
    asm volatile("ldmatrix.sync.aligned.m8n8.x4.shared.b16 {%0,%1,%2,%3}, [%4];"
                 : "=r"(r[0]), "=r"(r[1]), "=r"(r[2]), "=r"(r[3])
                 : "r"(saddr));
}

__device__ __forceinline__ void bar_sync(int id, int cnt) {
    asm volatile("bar.sync %0, %1;" :: "r"(id), "r"(cnt) : "memory");
}
__device__ __forceinline__ void bar_arrive(int id, int cnt) {
    asm volatile("bar.arrive %0, %1;" :: "r"(id), "r"(cnt) : "memory");
}

// split (x0, x1) into hi/lo bf16x2 words (lower 16 bits = x0)
__device__ __forceinline__ void bf16_split2(float x0, float x1,
                                            uint32_t& hw, uint32_t& lw) {
    asm("cvt.rn.bf16x2.f32 %0, %1, %2;" : "=r"(hw) : "f"(x1), "f"(x0));
    const float h0 = __uint_as_float(hw << 16);
    const float h1 = __uint_as_float(hw & 0xffff0000u);
    const float r0 = x0 - h0;
    const float r1 = x1 - h1;
    asm("cvt.rn.bf16x2.f32 %0, %1, %2;" : "=r"(lw) : "f"(r1), "f"(r0));
}

__device__ __forceinline__ void mma_bf16(float (&d)[4], const uint32_t (&a)[4],
                                         uint32_t b0, uint32_t b1) {
    asm("mma.sync.aligned.m16n8k16.row.col.f32.bf16.bf16.f32 "
        "{%0,%1,%2,%3}, {%4,%5,%6,%7}, {%8,%9}, {%0,%1,%2,%3};"
        : "+f"(d[0]), "+f"(d[1]), "+f"(d[2]), "+f"(d[3])
        : "r"(a[0]), "r"(a[1]), "r"(a[2]), "r"(a[3]), "r"(b0), "r"(b1));
}

// 16 floats of one row-half -> 8 hi + 8 lo words at swizzled quads i0, i0^4
__device__ __forceinline__ void stage_half(uint32_t* hiT, uint32_t* loT,
                                           uint32_t i0, const float4 f[4]) {
    uint4 h0, h1, l0, l1;
    bf16_split2(f[0].x, f[0].y, h0.x, l0.x);
    bf16_split2(f[0].z, f[0].w, h0.y, l0.y);
    bf16_split2(f[1].x, f[1].y, h0.z, l0.z);
    bf16_split2(f[1].z, f[1].w, h0.w, l0.w);
    bf16_split2(f[2].x, f[2].y, h1.x, l1.x);
    bf16_split2(f[2].z, f[2].w, h1.y, l1.y);
    bf16_split2(f[3].x, f[3].y, h1.z, l1.z);
    bf16_split2(f[3].z, f[3].w, h1.w, l1.w);
    *(uint4*)(hiT + i0)        = h0;
    *(uint4*)(hiT + (i0 ^ 4u)) = h1;
    *(uint4*)(loT + i0)        = l0;
    *(uint4*)(loT + (i0 ^ 4u)) = l1;
}

// ---------------------------------------------------------------------------
// C[bm,bn tile] = A(MxK, lda, row-major) * B^T, B is [N,K] row-major (ldb).
// 384 threads: 8 consumer warps (4x2 grid, 32x64 tiles) + 4 producer warps.
// ---------------------------------------------------------------------------
template<bool KLIM>
__device__ __forceinline__ void
gemm_core(const float* __restrict__ A, const float* __restrict__ Bm,
          float* __restrict__ C, int N, int K, int lda, int ldb,
          int bm, int bn)
{
    const int kEnd   = KLIM ? min(K, (bm + 1) * BM) : K;
    const int nchunk = kEnd / BK;

    extern __shared__ uint32_t sm[];
    const uint32_t smb = smem_u32(sm);

    const int tid  = threadIdx.x;
    const int wid  = tid >> 5;
    const int lane = tid & 31;

    if (wid < 8) {
        // ================= CONSUMER =================
        const int wm = wid & 3;             // 4 warps along M
        const int wn = wid >> 2;            // 2 warps along N
        const int g  = lane >> 2;
        const int c  = lane & 3;
        const int l8 = lane & 7;
        const int lm = lane >> 3;           // ldmatrix matrix id 0..3

        uint32_t relA[2][2], relB[4][2];
        #pragma unroll
        for (int mi = 0; mi < 2; mi++) {
            const uint32_t row = wm * 32 + mi * 16 + ((lm & 1) << 3) + l8;
            const uint32_t w   = (lm >> 1) << 2;
            relA[mi][0] = tile_addr(row, w) * 4u;
            relA[mi][1] = tile_addr(row, w + 8) * 4u;
        }
        #pragma unroll
        for (int p = 0; p < 4; p++) {
            const uint32_t row = wn * 64 + p * 16 + ((lm >> 1) << 3) + l8;
            const uint32_t w   = (lm & 1) << 2;
            relB[p][0] = tile_addr(row, w) * 4u;
            relB[p][1] = tile_addr(row, w + 8) * 4u;
        }

        float acc[2][8][4];
        #pragma unroll
        for (int mi = 0; mi < 2; mi++)
            #pragma unroll
            for (int ni = 0; ni < 8; ni++)
                #pragma unroll
                for (int q = 0; q < 4; q++) acc[mi][ni][q] = 0.f;

        for (int ic = 0; ic < nchunk; ic++) {
            const int st = ic & 1;
            bar_sync(st, NTHREADS);                 // wait full[st]

            const uint32_t bAh = smb + st * (STAGE_W * 4);
            const uint32_t bAl = bAh + TILE_W * 4;
            const uint32_t bBh = bAh + 2 * (TILE_W * 4);
            const uint32_t bBl = bAh + 3 * (TILE_W * 4);

            #pragma unroll
            for (int kt = 0; kt < 2; kt++) {
                uint32_t ah[2][4], al[2][4], bh[4][4], bl[4][4];
                #pragma unroll
                for (int mi = 0; mi < 2; mi++) {
                    ldsm_x4(ah[mi], bAh + relA[mi][kt]);
                    ldsm_x4(al[mi], bAl + relA[mi][kt]);
                }
                #pragma unroll
                for (int p = 0; p < 4; p++) {
                    ldsm_x4(bh[p], bBh + relB[p][kt]);
                    ldsm_x4(bl[p], bBl + relB[p][kt]);
                }
                #pragma unroll
                for (int mi = 0; mi < 2; mi++)
                    #pragma unroll
                    for (int ni = 0; ni < 8; ni++)
                        mma_bf16(acc[mi][ni], ah[mi],
                                 bh[ni >> 1][(ni & 1) * 2],
                                 bh[ni >> 1][(ni & 1) * 2 + 1]);
                #pragma unroll
                for (int mi = 0; mi < 2; mi++)
                    #pragma unroll
                    for (int ni = 0; ni < 8; ni++)
                        mma_bf16(acc[mi][ni], al[mi],
                                 bh[ni >> 1][(ni & 1) * 2],
                                 bh[ni >> 1][(ni & 1) * 2 + 1]);
                #pragma unroll
                for (int mi = 0; mi < 2; mi++)
                    #pragma unroll
                    for (int ni = 0; ni < 8; ni++)
                        mma_bf16(acc[mi][ni], ah[mi],
                                 bl[ni >> 1][(ni & 1) * 2],
                                 bl[ni >> 1][(ni & 1) * 2 + 1]);
            }
            bar_arrive(2 + st, NTHREADS);           // signal free[st]
        }

        // epilogue
        #pragma unroll
        for (int mi = 0; mi < 2; mi++) {
            const int r0 = bm * BM + wm * 32 + mi * 16 + g;
            #pragma unroll
            for (int ni = 0; ni < 8; ni++) {
                const int cc = bn * BN + wn * 64 + ni * 8 + c * 2;
                float2 v0 = make_float2(acc[mi][ni][0], acc[mi][ni][1]);
                float2 v1 = make_float2(acc[mi][ni][2], acc[mi][ni][3]);
                *(float2*)(C + (long long)r0 * N + cc)       = v0;
                *(float2*)(C + (long long)(r0 + 8) * N + cc) = v1;
            }
        }
    } else {
        // ================= PRODUCER =================
        const int pt = tid - 256;                   // 0..127 == staged row
        const float* Ap = A + (long long)(bm * BM + pt) * lda;
        const float* Bp = Bm + (long long)(bn * BN + pt) * ldb;
        const uint32_t sA0 = tile_addr(pt, 0);
        const uint32_t sA1 = tile_addr(pt, 8);

        for (int jc = 0; jc < nchunk; jc++) {
            const int st = jc & 1;
            if (jc >= 2) bar_sync(2 + st, NTHREADS);   // wait free[st]

            uint32_t* Sb = sm + st * STAGE_W;
            const float* ap = Ap + jc * BK;
            const float* bp = Bp + jc * BK;
            float4 f[4];

            f[0] = *(const float4*)(ap + 0);
            f[1] = *(const float4*)(ap + 4);
            f[2] = *(const float4*)(ap + 8);
            f[3] = *(const float4*)(ap + 12);
            stage_half(Sb, Sb + TILE_W, sA0, f);
            f[0] = *(const float4*)(ap + 16);
            f[1] = *(const float4*)(ap + 20);
            f[2] = *(const float4*)(ap + 24);
            f[3] = *(const float4*)(ap + 28);
            stage_half(Sb, Sb + TILE_W, sA1, f);

            f[0] = *(const float4*)(bp + 0);
            f[1] = *(const float4*)(bp + 4);
            f[2] = *(const float4*)(bp + 8);
            f[3] = *(const float4*)(bp + 12);
            stage_half(Sb + 2 * TILE_W, Sb + 3 * TILE_W, sA0, f);
            f[0] = *(const float4*)(bp + 16);
            f[1] = *(const float4*)(bp + 20);
            f[2] = *(const float4*)(bp + 24);
            f[3] = *(const float4*)(bp + 28);
            stage_half(Sb + 2 * TILE_W, Sb + 3 * TILE_W, sA1, f);

            __threadfence_block();                  // release
            bar_arrive(st, NTHREADS);               // signal full[st]
        }
    }
}

// ---- kernels ---------------------------------------------------------------
__global__ void __launch_bounds__(NTHREADS, 1)
k_qkv(const float* __restrict__ x, const float* __restrict__ wt,
      float* __restrict__ q, float* __restrict__ k, float* __restrict__ v)
{
    const float* W = wt + (size_t)blockIdx.z * D * D;   // W^T: [d_out][d_in]
    float* out = blockIdx.z == 0 ? q : (blockIdx.z == 1 ? k : v);
    gemm_core<false>(x, W, out, D, D, D, D, blockIdx.y, blockIdx.x);
}

__global__ void __launch_bounds__(NTHREADS, 1)
k_scores(const float* __restrict__ q, const float* __restrict__ kk,
         float* __restrict__ sc)
{
    if ((int)blockIdx.x > (int)blockIdx.y) return;      // causal block skip
    const size_t z = blockIdx.z;
    gemm_core<false>(q + z * (size_t)S * D, kk + z * (size_t)S * D,
                     sc + z * (size_t)S * S, S, D, D, D, blockIdx.y, blockIdx.x);
}

__global__ void __launch_bounds__(NTHREADS, 1)
k_pv(const float* __restrict__ sc, const float* __restrict__ vt,
     float* __restrict__ out)
{
    const size_t z = blockIdx.z;
    gemm_core<true>(sc + z * (size_t)S * S, vt + z * (size_t)D * S,
                    out + z * (size_t)S * D, D, S, S, S,
                    blockIdx.y, blockIdx.x);
}

// ---- transposes ------------------------------------------------------------
__global__ void __launch_bounds__(256)
k_wt(const float* __restrict__ wq, const float* __restrict__ wk,
     const float* __restrict__ wv, float* __restrict__ wt)
{
    __shared__ float t[32][33];
    const float* src = blockIdx.z == 0 ? wq : (blockIdx.z == 1 ? wk : wv);
    float* dst = wt + (size_t)blockIdx.z * D * D;
    const int r0 = blockIdx.x << 5, c0 = blockIdx.y << 5;
    const int tx = threadIdx.x & 31, ty = threadIdx.x >> 5;
    #pragma unroll
    for (int i = 0; i < 32; i += 8)
        t[ty + i][tx] = src[(size_t)(r0 + ty + i) * D + c0 + tx];
    __syncthreads();
    #pragma unroll
    for (int i = 0; i < 32; i += 8)
        dst[(size_t)(c0 + ty + i) * D + r0 + tx] = t[tx][ty + i];
}

__global__ void __launch_bounds__(256)
k_vt(const float* __restrict__ v, float* __restrict__ vt)
{
    __shared__ float t[32][33];
    const float* sp = v  + (size_t)blockIdx.z * S * D;
    float*       dp = vt + (size_t)blockIdx.z * D * S;
    const int s0 = blockIdx.x << 5, d0 = blockIdx.y << 5;
    const int tx = threadIdx.x & 31, ty = threadIdx.x >> 5;
    #pragma unroll
    for (int i = 0; i < 32; i += 8)
        t[ty + i][tx] = sp[(size_t)(s0 + ty + i) * D + d0 + tx];
    __syncthreads();
    #pragma unroll
    for (int i = 0; i < 32; i += 8)
        dp[(size_t)(d0 + ty + i) * S + s0 + tx] = t[tx][ty + i];
}

// ---- softmax ---------------------------------------------------------------
__global__ void __launch_bounds__(256)
softmax_causal(float* __restrict__ sc)
{
    const int r = blockIdx.x;
    const int b = r >> 12;
    const int i = r & (S - 1);
    float* row = sc + ((long long)b * S * S) + ((long long)i * S);
    const int n  = i + 1;
    const int n4 = n & ~3;
    const int tid  = threadIdx.x;
    const int wid  = tid >> 5;
    const int lane = tid & 31;
    const float scale = 0.03125f;   // 1/sqrt(1024)

    __shared__ float shm[8], shs[8];

    auto upd = [&](float& m, float& s, float v) {
        if (v <= m) s += __expf((v - m) * scale);
        else { s = s * __expf((m - v) * scale) + 1.f; m = v; }
    };

    float m = -3.0e38f, s = 0.f;
    for (int j = tid * 4; j < n4; j += 1024) {
        float4 vv = *(const float4*)(row + j);
        upd(m, s, vv.x); upd(m, s, vv.y); upd(m, s, vv.z); upd(m, s, vv.w);
    }
    for (int j = n4 + tid; j < n; j += 256) upd(m, s, row[j]);

    #pragma unroll
    for (int o = 16; o > 0; o >>= 1) {
        float mo = __shfl_xor_sync(0xffffffffu, m, o);
        float so = __shfl_xor_sync(0xffffffffu, s, o);
        float M  = fmaxf(m, mo);
        s = s * __expf((m - M) * scale) + so * __expf((mo - M) * scale);
        m = M;
    }
    if (lane == 0) { shm[wid] = m; shs[wid] = s; }
    __syncthreads();
    float M = shm[0], Sm = shs[0];
    #pragma unroll
    for (int t = 1; t < 8; t++) {
        float mo = shm[t], so = shs[t];
        float Mx = fmaxf(M, mo);
        Sm = Sm * __expf((M - Mx) * scale) + so * __expf((mo - Mx) * scale);
        M = Mx;
    }
    const float inv = 1.0f / Sm;

    for (int j = tid * 4; j < n4; j += 1024) {
        float4 vv = *(const float4*)(row + j);
        vv.x = __expf((vv.x - M) * scale) * inv;
        vv.y = __expf((vv.y - M) * scale) * inv;
        vv.z = __expf((vv.z - M) * scale) * inv;
        vv.w = __expf((vv.w - M) * scale) * inv;
        *(float4*)(row + j) = vv;
    }
    for (int j = n4 + tid; j < n; j += 256)
        row[j] = __expf((row[j] - M) * scale) * inv;

    const int end = ((i >> 7) + 1) << 7;
    for (int j = n + tid; j < end; j += 256) row[j] = 0.f;
}

// ---------------------------------------------------------------------------
extern "C" void kernel_launch(void* const* d_in, const int* in_sizes, int n_in,
                              void* d_out, int out_size)
{
    const float* x  = (const float*)d_in[0];
    const float* Wq = (const float*)d_in[1];
    const float* Wk = (const float*)d_in[2];
    const float* Wv = (const float*)d_in[3];
    float* out = (float*)d_out;

    static float *q = nullptr, *k = nullptr, *v = nullptr, *vt = nullptr,
                 *wt = nullptr, *sc = nullptr;
    static bool init = false;
    if (!init) {
        cudaGetSymbolAddress((void**)&q,  g_q);
        cudaGetSymbolAddress((void**)&k,  g_k);
        cudaGetSymbolAddress((void**)&v,  g_v);
        cudaGetSymbolAddress((void**)&vt, g_vt);
        cudaGetSymbolAddress((void**)&wt, g_wt);
        cudaGetSymbolAddress((void**)&sc, g_s);
        cudaFuncSetAttribute(k_qkv,
                             cudaFuncAttributeMaxDynamicSharedMemorySize, SMEM_BYTES);
        cudaFuncSetAttribute(k_scores,
                             cudaFuncAttributeMaxDynamicSharedMemorySize, SMEM_BYTES);
        cudaFuncSetAttribute(k_pv,
                             cudaFuncAttributeMaxDynamicSharedMemorySize, SMEM_BYTES);
        init = true;
    }

    // 1) W^T (B operand is [N,K] = [d_out][d_in])
    k_wt<<<dim3(D / 32, D / 32, 3), 256>>>(Wq, Wk, Wv, wt);

    // 2) QKV projections
    k_qkv<<<dim3(D / BN, (Bb * S) / BM, 3), NTHREADS, SMEM_BYTES>>>(
        x, wt, q, k, v);

    // 3) V^T for PV
    k_vt<<<dim3(S / 32, D / 32, Bb), 256>>>(v, vt);

    // 4) scores = Q K^T  (K's natural [S,D] layout is the [N,K] operand)
    k_scores<<<dim3(S / BN, S / BM, Bb), NTHREADS, SMEM_BYTES>>>(q, k, sc);

    // 5) softmax
    softmax_causal<<<Bb * S, 256>>>(sc);

    // 6) out = P V  (B = V^T)
    k_pv<<<dim3(D / BN, S / BM, Bb), NTHREADS, SMEM_BYTES>>>(sc, vt, out);
}

// round 10
// speedup vs baseline: 1.2132x; 1.2132x over previous
#include <cuda_runtime.h>
#include <cstdint>

// ============================================================================
// CausalAttention, B=4, S=4096, D=1024, fp32 in/out.
// bf16x3-split mma.sync m16n8k16 GEMMs; hi/lo bf16x2 tiles in pair-line
// swizzled smem; ldmatrix.x4 fragment loads. 256 thr/CTA, 4x2 warps, 32x64
// warp tiles, double buffer. Chunk schedule overlaps STS(i+1) and LDG(i+2)
// under the MMA stream: LDSM kt0 | STS next | LDSM kt1 | MMA kt0 | LDG | MMA
// kt1 | sync.  (R9 warp-specialization reverted: it raised crossbar traffic.)
// ============================================================================

static constexpr int Bb = 4;
static constexpr int S  = 4096;
static constexpr int D  = 1024;
static constexpr int BM = 128;
static constexpr int BN = 128;
static constexpr int BK = 32;                 // floats per chunk (16 words)

static constexpr int TILE_W    = 2048;        // words per [128][16] tile (8 KB)
static constexpr int STAGE_W   = 4 * TILE_W;  // Ah, Al, Bh, Bl
static constexpr int SMEM_BYTES = 2 * STAGE_W * 4;   // 65536

static __device__ float g_q [(size_t)Bb * S * D];
static __device__ float g_k [(size_t)Bb * S * D];
static __device__ float g_v [(size_t)Bb * S * D];
static __device__ float g_vt[(size_t)Bb * D * S];
static __device__ float g_wt[(size_t)3 * D * D];
static __device__ float g_s [(size_t)Bb * S * S];

// ---------------------------------------------------------------------------
__device__ __forceinline__ uint32_t tile_addr(uint32_t row, uint32_t w) {
    const uint32_t line = row >> 1;
    const uint32_t off  = ((row & 1u) << 4) + w;
    return line * 32u + (off ^ ((line & 7u) << 2));
}

__device__ __forceinline__ uint32_t smem_u32(const void* p) {
    uint32_t a;
    asm("{ .reg .u64 t; cvta.to.shared.u64 t, %1; cvt.u32.u64 %0, t; }"
        : "=r"(a) : "l"(p));
    return a;
}

__device__ __forceinline__ void ldsm_x4(uint32_t (&r)[4], uint32_t saddr) {
    asm volatile("ldmatrix.sync.aligned.m8n8.x4.shared.b16 {%0,%1,%2,%3}, [%4];"
                 : "=r"(r[0]), "=r"(r[1]), "=r"(r[2]), "=r"(r[3])
                 : "r"(saddr));
}

// split (x0, x1) into hi/lo bf16x2 words (lower 16 bits = x0)
__device__ __forceinline__ void bf16_split2(float x0, float x1,
                                            uint32_t& hw, uint32_t& lw) {
    asm("cvt.rn.bf16x2.f32 %0, %1, %2;" : "=r"(hw) : "f"(x1), "f"(x0));
    const float h0 = __uint_as_float(hw << 16);
    const float h1 = __uint_as_float(hw & 0xffff0000u);
    const float r0 = x0 - h0;
    const float r1 = x1 - h1;
    asm("cvt.rn.bf16x2.f32 %0, %1, %2;" : "=r"(lw) : "f"(r1), "f"(r0));
}

__device__ __forceinline__ void mma_bf16(float (&d)[4], const uint32_t (&a)[4],
                                         uint32_t b0, uint32_t b1) {
    asm("mma.sync.aligned.m16n8k16.row.col.f32.bf16.bf16.f32 "
        "{%0,%1,%2,%3}, {%4,%5,%6,%7}, {%8,%9}, {%0,%1,%2,%3};"
        : "+f"(d[0]), "+f"(d[1]), "+f"(d[2]), "+f"(d[3])
        : "r"(a[0]), "r"(a[1]), "r"(a[2]), "r"(a[3]), "r"(b0), "r"(b1));
}

__device__ __forceinline__ void stage_half(uint32_t* hiT, uint32_t* loT,
                                           uint32_t i0, const float4 f[4]) {
    uint4 h0, h1, l0, l1;
    bf16_split2(f[0].x, f[0].y, h0.x, l0.x);
    bf16_split2(f[0].z, f[0].w, h0.y, l0.y);
    bf16_split2(f[1].x, f[1].y, h0.z, l0.z);
    bf16_split2(f[1].z, f[1].w, h0.w, l0.w);
    bf16_split2(f[2].x, f[2].y, h1.x, l1.x);
    bf16_split2(f[2].z, f[2].w, h1.y, l1.y);
    bf16_split2(f[3].x, f[3].y, h1.z, l1.z);
    bf16_split2(f[3].z, f[3].w, h1.w, l1.w);
    *(uint4*)(hiT + i0)        = h0;
    *(uint4*)(hiT + (i0 ^ 4u)) = h1;
    *(uint4*)(loT + i0)        = l0;
    *(uint4*)(loT + (i0 ^ 4u)) = l1;
}

// ---------------------------------------------------------------------------
// C[bm,bn tile] = A(MxK, lda, row-major) * B^T, B is [N,K] row-major (ldb).
// 256 threads. KLIM: K limited to (bm+1)*BM.
// ---------------------------------------------------------------------------
template<bool KLIM>
__device__ __forceinline__ void
gemm_core(const float* __restrict__ A, const float* __restrict__ Bm,
          float* __restrict__ C, int N, int K, int lda, int ldb,
          int bm, int bn)
{
    const int kEnd   = KLIM ? min(K, (bm + 1) * BM) : K;
    const int nchunk = kEnd / BK;

    extern __shared__ uint32_t sm[];
    const uint32_t smb = smem_u32(sm);

    const int tid  = threadIdx.x;
    const int wid  = tid >> 5;
    const int wm   = wid & 3;               // 4 warps along M
    const int wn   = wid >> 2;              // 2 warps along N
    const int lane = tid & 31;
    const int g    = lane >> 2;
    const int c    = lane & 3;
    const int l8   = lane & 7;
    const int lm   = lane >> 3;             // ldmatrix matrix id 0..3

    uint32_t relA[2][2], relB[4][2];
    #pragma unroll
    for (int mi = 0; mi < 2; mi++) {
        const uint32_t row = wm * 32 + mi * 16 + ((lm & 1) << 3) + l8;
        const uint32_t w   = (lm >> 1) << 2;
        relA[mi][0] = tile_addr(row, w) * 4u;
        relA[mi][1] = tile_addr(row, w + 8) * 4u;
    }
    #pragma unroll
    for (int p = 0; p < 4; p++) {
        const uint32_t row = wn * 64 + p * 16 + ((lm >> 1) << 3) + l8;
        const uint32_t w   = (lm & 1) << 2;
        relB[p][0] = tile_addr(row, w) * 4u;
        relB[p][1] = tile_addr(row, w + 8) * 4u;
    }

    // staging map: thread t -> row t>>1, k-half h = t&1 (16 floats)
    const int srow = tid >> 1;
    const int h    = tid & 1;
    const uint32_t stA = tile_addr(srow, h * 8);
    const float* Ap = A + (long long)(bm * BM + srow) * lda + h * 16;
    const float* Bp = Bm + (long long)(bn * BN + srow) * ldb + h * 16;

    float4 pa[4], pb[4];
    #pragma unroll
    for (int i = 0; i < 4; i++) {
        pa[i] = *(const float4*)(Ap + i * 4);
        pb[i] = *(const float4*)(Bp + i * 4);
    }
    {   // stage chunk 0 into stage 0
        stage_half(sm,              sm + TILE_W,     stA, pa);
        stage_half(sm + 2 * TILE_W, sm + 3 * TILE_W, stA, pb);
    }
    if (nchunk > 1) {   // preload chunk 1 into regs
        #pragma unroll
        for (int i = 0; i < 4; i++) {
            pa[i] = *(const float4*)(Ap + BK + i * 4);
            pb[i] = *(const float4*)(Bp + BK + i * 4);
        }
    }
    __syncthreads();

    float acc[2][8][4];
    #pragma unroll
    for (int mi = 0; mi < 2; mi++)
        #pragma unroll
        for (int ni = 0; ni < 8; ni++)
            #pragma unroll
            for (int q = 0; q < 4; q++) acc[mi][ni][q] = 0.f;

    for (int ic = 0; ic < nchunk; ic++) {
        const int st = ic & 1;
        const uint32_t bAh = smb + st * (STAGE_W * 4);
        const uint32_t bAl = bAh + TILE_W * 4;
        const uint32_t bBh = bAh + 2 * (TILE_W * 4);
        const uint32_t bBl = bAh + 3 * (TILE_W * 4);

        uint32_t ah[2][2][4], al[2][2][4], bh[2][4][4], bl[2][4][4];

        // 1. fragments for kt=0
        #pragma unroll
        for (int mi = 0; mi < 2; mi++) {
            ldsm_x4(ah[0][mi], bAh + relA[mi][0]);
            ldsm_x4(al[0][mi], bAl + relA[mi][0]);
        }
        #pragma unroll
        for (int p = 0; p < 4; p++) {
            ldsm_x4(bh[0][p], bBh + relB[p][0]);
            ldsm_x4(bl[0][p], bBl + relB[p][0]);
        }

        // 2. STS chunk ic+1 into the other stage (free since last sync)
        if (ic + 1 < nchunk) {
            uint32_t* nS = sm + (st ^ 1) * STAGE_W;
            stage_half(nS,              nS + TILE_W,     stA, pa);
            stage_half(nS + 2 * TILE_W, nS + 3 * TILE_W, stA, pb);
        }

        // 3. fragments for kt=1
        #pragma unroll
        for (int mi = 0; mi < 2; mi++) {
            ldsm_x4(ah[1][mi], bAh + relA[mi][1]);
            ldsm_x4(al[1][mi], bAl + relA[mi][1]);
        }
        #pragma unroll
        for (int p = 0; p < 4; p++) {
            ldsm_x4(bh[1][p], bBh + relB[p][1]);
            ldsm_x4(bl[1][p], bBl + relB[p][1]);
        }

        // 4. MMAs kt=0 (grouped by split term; distinct accumulators)
        #pragma unroll
        for (int mi = 0; mi < 2; mi++)
            #pragma unroll
            for (int ni = 0; ni < 8; ni++)
                mma_bf16(acc[mi][ni], ah[0][mi],
                         bh[0][ni >> 1][(ni & 1) * 2],
                         bh[0][ni >> 1][(ni & 1) * 2 + 1]);
        #pragma unroll
        for (int mi = 0; mi < 2; mi++)
            #pragma unroll
            for (int ni = 0; ni < 8; ni++)
                mma_bf16(acc[mi][ni], al[0][mi],
                         bh[0][ni >> 1][(ni & 1) * 2],
                         bh[0][ni >> 1][(ni & 1) * 2 + 1]);
        #pragma unroll
        for (int mi = 0; mi < 2; mi++)
            #pragma unroll
            for (int ni = 0; ni < 8; ni++)
                mma_bf16(acc[mi][ni], ah[0][mi],
                         bl[0][ni >> 1][(ni & 1) * 2],
                         bl[0][ni >> 1][(ni & 1) * 2 + 1]);

        // 5. LDG chunk ic+2 into regs
        if (ic + 2 < nchunk) {
            const int kn = (ic + 2) * BK;
            #pragma unroll
            for (int i = 0; i < 4; i++) {
                pa[i] = *(const float4*)(Ap + kn + i * 4);
                pb[i] = *(const float4*)(Bp + kn + i * 4);
            }
        }

        // 6. MMAs kt=1
        #pragma unroll
        for (int mi = 0; mi < 2; mi++)
            #pragma unroll
            for (int ni = 0; ni < 8; ni++)
                mma_bf16(acc[mi][ni], ah[1][mi],
                         bh[1][ni >> 1][(ni & 1) * 2],
                         bh[1][ni >> 1][(ni & 1) * 2 + 1]);
        #pragma unroll
        for (int mi = 0; mi < 2; mi++)
            #pragma unroll
            for (int ni = 0; ni < 8; ni++)
                mma_bf16(acc[mi][ni], al[1][mi],
                         bh[1][ni >> 1][(ni & 1) * 2],
                         bh[1][ni >> 1][(ni & 1) * 2 + 1]);
        #pragma unroll
        for (int mi = 0; mi < 2; mi++)
            #pragma unroll
            for (int ni = 0; ni < 8; ni++)
                mma_bf16(acc[mi][ni], ah[1][mi],
                         bl[1][ni >> 1][(ni & 1) * 2],
                         bl[1][ni >> 1][(ni & 1) * 2 + 1]);

        __syncthreads();
    }

    // epilogue
    #pragma unroll
    for (int mi = 0; mi < 2; mi++) {
        const int r0 = bm * BM + wm * 32 + mi * 16 + g;
        #pragma unroll
        for (int ni = 0; ni < 8; ni++) {
            const int cc = bn * BN + wn * 64 + ni * 8 + c * 2;
            float2 v0 = make_float2(acc[mi][ni][0], acc[mi][ni][1]);
            float2 v1 = make_float2(acc[mi][ni][2], acc[mi][ni][3]);
            *(float2*)(C + (long long)r0 * N + cc)       = v0;
            *(float2*)(C + (long long)(r0 + 8) * N + cc) = v1;
        }
    }
}

// ---- kernels ---------------------------------------------------------------
__global__ void __launch_bounds__(256, 1)
k_qkv(const float* __restrict__ x, const float* __restrict__ wt,
      float* __restrict__ q, float* __restrict__ k, float* __restrict__ v)
{
    const float* W = wt + (size_t)blockIdx.z * D * D;   // W^T: [d_out][d_in]
    float* out = blockIdx.z == 0 ? q : (blockIdx.z == 1 ? k : v);
    gemm_core<false>(x, W, out, D, D, D, D, blockIdx.y, blockIdx.x);
}

__global__ void __launch_bounds__(256, 1)
k_scores(const float* __restrict__ q, const float* __restrict__ kk,
         float* __restrict__ sc)
{
    if ((int)blockIdx.x > (int)blockIdx.y) return;      // causal block skip
    const size_t z = blockIdx.z;
    gemm_core<false>(q + z * (size_t)S * D, kk + z * (size_t)S * D,
                     sc + z * (size_t)S * S, S, D, D, D, blockIdx.y, blockIdx.x);
}

__global__ void __launch_bounds__(256, 1)
k_pv(const float* __restrict__ sc, const float* __restrict__ vt,
     float* __restrict__ out)
{
    const size_t z = blockIdx.z;
    gemm_core<true>(sc + z * (size_t)S * S, vt + z * (size_t)D * S,
                    out + z * (size_t)S * D, D, S, S, S,
                    blockIdx.y, blockIdx.x);
}

// ---- transposes ------------------------------------------------------------
__global__ void __launch_bounds__(256)
k_wt(const float* __restrict__ wq, const float* __restrict__ wk,
     const float* __restrict__ wv, float* __restrict__ wt)
{
    __shared__ float t[32][33];
    const float* src = blockIdx.z == 0 ? wq : (blockIdx.z == 1 ? wk : wv);
    float* dst = wt + (size_t)blockIdx.z * D * D;
    const int r0 = blockIdx.x << 5, c0 = blockIdx.y << 5;
    const int tx = threadIdx.x & 31, ty = threadIdx.x >> 5;
    #pragma unroll
    for (int i = 0; i < 32; i += 8)
        t[ty + i][tx] = src[(size_t)(r0 + ty + i) * D + c0 + tx];
    __syncthreads();
    #pragma unroll
    for (int i = 0; i < 32; i += 8)
        dst[(size_t)(c0 + ty + i) * D + r0 + tx] = t[tx][ty + i];
}

__global__ void __launch_bounds__(256)
k_vt(const float* __restrict__ v, float* __restrict__ vt)
{
    __shared__ float t[32][33];
    const float* sp = v  + (size_t)blockIdx.z * S * D;
    float*       dp = vt + (size_t)blockIdx.z * D * S;
    const int s0 = blockIdx.x << 5, d0 = blockIdx.y << 5;
    const int tx = threadIdx.x & 31, ty = threadIdx.x >> 5;
    #pragma unroll
    for (int i = 0; i < 32; i += 8)
        t[ty + i][tx] = sp[(size_t)(s0 + ty + i) * D + d0 + tx];
    __syncthreads();
    #pragma unroll
    for (int i = 0; i < 32; i += 8)
        dp[(size_t)(d0 + ty + i) * S + s0 + tx] = t[tx][ty + i];
}

// ---- softmax ---------------------------------------------------------------
__global__ void __launch_bounds__(256)
softmax_causal(float* __restrict__ sc)
{
    const int r = blockIdx.x;
    const int b = r >> 12;
    const int i = r & (S - 1);
    float* row = sc + ((long long)b * S * S) + ((long long)i * S);
    const int n  = i + 1;
    const int n4 = n & ~3;
    const int tid  = threadIdx.x;
    const int wid  = tid >> 5;
    const int lane = tid & 31;
    const float scale = 0.03125f;   // 1/sqrt(1024)

    __shared__ float shm[8], shs[8];

    auto upd = [&](float& m, float& s, float v) {
        if (v <= m) s += __expf((v - m) * scale);
        else { s = s * __expf((m - v) * scale) + 1.f; m = v; }
    };

    float m = -3.0e38f, s = 0.f;
    for (int j = tid * 4; j < n4; j += 1024) {
        float4 vv = *(const float4*)(row + j);
        upd(m, s, vv.x); upd(m, s, vv.y); upd(m, s, vv.z); upd(m, s, vv.w);
    }
    for (int j = n4 + tid; j < n; j += 256) upd(m, s, row[j]);

    #pragma unroll
    for (int o = 16; o > 0; o >>= 1) {
        float mo = __shfl_xor_sync(0xffffffffu, m, o);
        float so = __shfl_xor_sync(0xffffffffu, s, o);
        float M  = fmaxf(m, mo);
        s = s * __expf((m - M) * scale) + so * __expf((mo - M) * scale);
        m = M;
    }
    if (lane == 0) { shm[wid] = m; shs[wid] = s; }
    __syncthreads();
    float M = shm[0], Sm = shs[0];
    #pragma unroll
    for (int t = 1; t < 8; t++) {
        float mo = shm[t], so = shs[t];
        float Mx = fmaxf(M, mo);
        Sm = Sm * __expf((M - Mx) * scale) + so * __expf((mo - Mx) * scale);
        M = Mx;
    }
    const float inv = 1.0f / Sm;

    for (int j = tid * 4; j < n4; j += 1024) {
        float4 vv = *(const float4*)(row + j);
        vv.x = __expf((vv.x - M) * scale) * inv;
        vv.y = __expf((vv.y - M) * scale) * inv;
        vv.z = __expf((vv.z - M) * scale) * inv;
        vv.w = __expf((vv.w - M) * scale) * inv;
        *(float4*)(row + j) = vv;
    }
    for (int j = n4 + tid; j < n; j += 256)
        row[j] = __expf((row[j] - M) * scale) * inv;

    const int end = ((i >> 7) + 1) << 7;
    for (int j = n + tid; j < end; j += 256) row[j] = 0.f;
}

// ---------------------------------------------------------------------------
extern "C" void kernel_launch(void* const* d_in, const int* in_sizes, int n_in,
                              void* d_out, int out_size)
{
    const float* x  = (const float*)d_in[0];
    const float* Wq = (const float*)d_in[1];
    const float* Wk = (const float*)d_in[2];
    const float* Wv = (const float*)d_in[3];
    float* out = (float*)d_out;

    static float *q = nullptr, *k = nullptr, *v = nullptr, *vt = nullptr,
                 *wt = nullptr, *sc = nullptr;
    static bool init = false;
    if (!init) {
        cudaGetSymbolAddress((void**)&q,  g_q);
        cudaGetSymbolAddress((void**)&k,  g_k);
        cudaGetSymbolAddress((void**)&v,  g_v);
        cudaGetSymbolAddress((void**)&vt, g_vt);
        cudaGetSymbolAddress((void**)&wt, g_wt);
        cudaGetSymbolAddress((void**)&sc, g_s);
        cudaFuncSetAttribute(k_qkv,
                             cudaFuncAttributeMaxDynamicSharedMemorySize, SMEM_BYTES);
        cudaFuncSetAttribute(k_scores,
                             cudaFuncAttributeMaxDynamicSharedMemorySize, SMEM_BYTES);
        cudaFuncSetAttribute(k_pv,
                             cudaFuncAttributeMaxDynamicSharedMemorySize, SMEM_BYTES);
        init = true;
    }

    // 1) W^T (B operand is [N,K] = [d_out][d_in])
    k_wt<<<dim3(D / 32, D / 32, 3), 256>>>(Wq, Wk, Wv, wt);

    // 2) QKV projections
    k_qkv<<<dim3(D / BN, (Bb * S) / BM, 3), 256, SMEM_BYTES>>>(x, wt, q, k, v);

    // 3) V^T for PV
    k_vt<<<dim3(S / 32, D / 32, Bb), 256>>>(v, vt);

    // 4) scores = Q K^T  (K's natural [S,D] layout is the [N,K] operand)
    k_scores<<<dim3(S / BN, S / BM, Bb), 256, SMEM_BYTES>>>(q, k, sc);

    // 5) softmax
    softmax_causal<<<Bb * S, 256>>>(sc);

    // 6) out = P V  (B = V^T)
    k_pv<<<dim3(D / BN, S / BM, Bb), 256, SMEM_BYTES>>>(sc, vt, out);
}